// round 11
// baseline (speedup 1.0000x reference)
#include <cuda_runtime.h>
#include <cuda_bf16.h>
#include <cstdint>
#include <cstring>

typedef unsigned long long u64;

// Scratch: packed float2 h-pairs, layout [sk][b][hp][n]
//   sk = side*8 + k (side0 = HI, side1 = HJ + b1), b 0..7, hp 0..63, n 0..255
__device__ __align__(16) float2 g_H2[16u * 8u * 64u * 256u];   // 16 MB (L2-resident)

// ---------------------------------------------------------------------------
// helpers
// ---------------------------------------------------------------------------
static __device__ __forceinline__ void cpa16(void* dst, const void* src) {
    uint32_t d = (uint32_t)__cvta_generic_to_shared(dst);
    asm volatile("cp.async.cg.shared.global [%0], [%1], 16;" :: "r"(d), "l"(src));
}
static __device__ __forceinline__ void cpa_commit() {
    asm volatile("cp.async.commit_group;");
}
template<int N> static __device__ __forceinline__ void cpa_wait() {
    asm volatile("cp.async.wait_group %0;" :: "n"(N));
}
static __device__ __forceinline__ void f2_unpack(u64 v, float& lo, float& hi) {
    asm("mov.b64 {%0, %1}, %2;" : "=f"(lo), "=f"(hi) : "l"(v));
}
// acc += relu(hs + hj) * wp  per f32 lane; single asm block so ptxas can
// register-rename the pack/unpack movs.
static __device__ __forceinline__ void relu_dot(u64& acc, u64 hs, u64 hj, u64 wp) {
    asm("{\n\t"
        ".reg .f32 lo, hi;\n\t"
        ".reg .b64 s;\n\t"
        "add.rn.f32x2 s, %1, %2;\n\t"
        "mov.b64 {lo, hi}, s;\n\t"
        "max.f32 lo, lo, 0f00000000;\n\t"
        "max.f32 hi, hi, 0f00000000;\n\t"
        "mov.b64 s, {lo, hi};\n\t"
        "fma.rn.f32x2 %0, s, %3, %0;\n\t"
        "}" : "+l"(acc) : "l"(hs), "l"(hj), "l"(wp));
}

// ---------------------------------------------------------------------------
// Kernel 1: HI / HJB = E @ W1_slice (+ b1 for side 1). UNCHANGED from R10
// (best measured config; compute-bound at the FFMA2 rate).
// ---------------------------------------------------------------------------
__global__ void __launch_bounds__(256, 2)
k1_gemm(const float* __restrict__ E, const float* __restrict__ W1,
        const float* __restrict__ b1)
{
    __shared__ __align__(16) float2 aS[2][16][128];  // [buf][d][m] dup, 32KB
    __shared__ __align__(16) float  bS[2][16][128];  // [buf][d][h],      16KB

    const int t     = threadIdx.x;
    const int mtile = blockIdx.x;          // 0..15
    const int sk    = blockIdx.y;          // 0..15
    const int k     = sk & 7;
    const int side  = sk >> 3;
    const float* Wb = W1 + (size_t)k * 32768 + (size_t)side * 16384; // [d][h]

    const int tn = t & 15, tm = t >> 4;        // compute mapping
    const int arow = t >> 2, adq = t & 3;      // A loader
    const int bd = t >> 5, bq = t & 31;        // B loader
    const int bd2 = bd + 8;

    u64 acc[8][4];
    #pragma unroll
    for (int v = 0; v < 8; ++v)
        #pragma unroll
        for (int u = 0; u < 4; ++u) acc[v][u] = 0ULL;

    // --- prologue ---
    float4 rA0, rA1;
    rA0 = *(const float4*)(E + (size_t)(mtile * 128 + arow) * 128 + 0 + adq * 4);
    rA1 = *(const float4*)(E + (size_t)(mtile * 128 + arow + 64) * 128 + 0 + adq * 4);
    {
        float x[4] = {rA0.x, rA0.y, rA0.z, rA0.w};
        float y[4] = {rA1.x, rA1.y, rA1.z, rA1.w};
        #pragma unroll
        for (int q = 0; q < 4; ++q) {
            aS[0][adq * 4 + q][arow]      = make_float2(x[q], x[q]);
            aS[0][adq * 4 + q][arow + 64] = make_float2(y[q], y[q]);
        }
    }
    rA0 = *(const float4*)(E + (size_t)(mtile * 128 + arow) * 128 + 16 + adq * 4);
    rA1 = *(const float4*)(E + (size_t)(mtile * 128 + arow + 64) * 128 + 16 + adq * 4);
    #pragma unroll
    for (int c = 0; c < 2; ++c) {
        cpa16(&bS[c][bd][bq * 4],  Wb + (size_t)(c * 16 + bd)  * 128 + bq * 4);
        cpa16(&bS[c][bd2][bq * 4], Wb + (size_t)(c * 16 + bd2) * 128 + bq * 4);
        cpa_commit();
    }

    #pragma unroll
    for (int c = 0; c < 8; ++c) {
        if (c < 7) cpa_wait<1>(); else cpa_wait<0>();
        __syncthreads();
        if (c + 1 < 8) {
            float x[4] = {rA0.x, rA0.y, rA0.z, rA0.w};
            float y[4] = {rA1.x, rA1.y, rA1.z, rA1.w};
            int nb = (c + 1) & 1;
            #pragma unroll
            for (int q = 0; q < 4; ++q) {
                aS[nb][adq * 4 + q][arow]      = make_float2(x[q], x[q]);
                aS[nb][adq * 4 + q][arow + 64] = make_float2(y[q], y[q]);
            }
        }
        const int buf = c & 1;
        #pragma unroll
        for (int d = 0; d < 16; ++d) {
            u64 b2r[4];
            #pragma unroll
            for (int u = 0; u < 4; ++u)
                b2r[u] = *(const u64*)&bS[buf][d][2 * (tn + 16 * u)];
            #pragma unroll
            for (int v = 0; v < 8; ++v) {
                u64 ad = *(const u64*)&aS[buf][d][tm * 8 + v];
                #pragma unroll
                for (int u = 0; u < 4; ++u)
                    asm("fma.rn.f32x2 %0, %1, %2, %0;"
                        : "+l"(acc[v][u]) : "l"(ad), "l"(b2r[u]));
            }
        }
        __syncthreads();
        if (c + 2 < 8) {
            int d0 = (c + 2) * 16;
            rA0 = *(const float4*)(E + (size_t)(mtile * 128 + arow) * 128 + d0 + adq * 4);
            rA1 = *(const float4*)(E + (size_t)(mtile * 128 + arow + 64) * 128 + d0 + adq * 4);
            cpa16(&bS[buf][bd][bq * 4],  Wb + (size_t)(d0 + bd)  * 128 + bq * 4);
            cpa16(&bS[buf][bd2][bq * 4], Wb + (size_t)(d0 + bd2) * 128 + bq * 4);
            cpa_commit();
        }
    }

    // epilogue: add b1 pair (side 1), store transposed [sk][b][hp][n]
    const int b     = mtile >> 1;
    const int nbase = (mtile & 1) * 128 + tm * 8;
    const float* b1k = b1 + k * 128;
    #pragma unroll
    for (int u = 0; u < 4; ++u) {
        int hp = tn + 16 * u;
        float bx = 0.0f, by = 0.0f;
        if (side) { bx = b1k[2 * hp]; by = b1k[2 * hp + 1]; }
        size_t rowbase = ((size_t)(sk * 8 + b) * 64 + hp) * 256;
        #pragma unroll
        for (int v = 0; v < 8; ++v) {
            float lo, hi; f2_unpack(acc[v][u], lo, hi);
            g_H2[rowbase + nbase + v] = make_float2(lo + bx, hi + by);
        }
    }
}

// ---------------------------------------------------------------------------
// Kernel 2: pair loop + entmax-1.5 closed form.
// NEW: tile 64i x 32j, 256 threads, 4i x 2j per thread (16 acc regs).
//   - 2048 blocks, 4 blocks/SM -> 3.46 waves @ 86.5% util (was 2.31 @ 77%)
//   - occ target 50% (32 warps/SM) for latency hiding
//   - single cp.async phase, ONE __syncthreads per block
// Dynamic smem:
//   hiS: float2 [64][64] at      0  (32768 B)
//   hjS: float2 [64][32] at  32768  (16384 B)
//   w2S: float2 [64]     at  49152  (  512 B)
// ---------------------------------------------------------------------------
#define K2_SMEM_BYTES (32768 + 16384 + 512)

__global__ void __launch_bounds__(256, 4)
k2_pairs(const float* __restrict__ W2, const float* __restrict__ b2,
         const float* __restrict__ W3, const float* __restrict__ b3,
         float* __restrict__ out)
{
    extern __shared__ __align__(16) char smem[];
    float2 (*hiS)[64] = (float2(*)[64])(smem);
    float2 (*hjS)[32] = (float2(*)[32])(smem + 32768);
    float2* w2S       = (float2*)(smem + 49152);

    const int t  = threadIdx.x;
    const int z  = blockIdx.z;
    const int b  = z >> 3, k = z & 7;
    const int i0 = blockIdx.y * 64;
    const int j0 = blockIdx.x * 32;

    if (t < 64) {
        const float* w2k = W2 + k * 256;   // [h][c]
        w2S[t] = make_float2(0.25f * (w2k[4 * t + 0] - w2k[4 * t + 1]),
                             0.25f * (w2k[4 * t + 2] - w2k[4 * t + 3]));
    }

    const float2* hib = g_H2 + ((size_t)(k * 8 + b) * 64) * 256 + i0;        // side 0
    const float2* hjb = g_H2 + ((size_t)((8 + k) * 8 + b) * 64) * 256 + j0;  // side 1

    // hi tile 64hp x 64i: 8 x 16B per thread; hj tile 64hp x 32j: 4 x 16B
    #pragma unroll
    for (int r = 0; r < 8; ++r) {
        int o = t + 256 * r;
        int p = o >> 5, q = o & 31;
        cpa16(&hiS[p][q * 2], hib + (size_t)p * 256 + q * 2);
    }
    #pragma unroll
    for (int r = 0; r < 4; ++r) {
        int o = t + 256 * r;
        int p = o >> 4, q = o & 15;
        cpa16(&hjS[p][q * 2], hjb + (size_t)p * 256 + q * 2);
    }
    cpa_commit();

    u64 acc[4][2];
    #pragma unroll
    for (int a = 0; a < 4; ++a) {
        acc[a][0] = 0ULL; acc[a][1] = 0ULL;
    }

    cpa_wait<0>();
    __syncthreads();    // the only barrier in the kernel

    const int tj = t & 15, ti = t >> 4;

    #pragma unroll 4
    for (int pp = 0; pp < 64; pp += 2) {
        ulonglong2 wpr = *(const ulonglong2*)&w2S[pp];   // 2 w-pairs, one LDS.128
        #pragma unroll
        for (int s = 0; s < 2; ++s) {
            const int p = pp + s;
            const u64 wp = s ? wpr.y : wpr.x;
            ulonglong2 h01 = *(const ulonglong2*)&hiS[p][ti * 4];
            ulonglong2 h23 = *(const ulonglong2*)&hiS[p][ti * 4 + 2];
            u64 hiv[4] = {h01.x, h01.y, h23.x, h23.y};
            u64 hj0 = *(const u64*)&hjS[p][tj];
            u64 hj1 = *(const u64*)&hjS[p][tj + 16];
            #pragma unroll
            for (int a = 0; a < 4; ++a) {
                relu_dot(acc[a][0], hiv[a], hj0, wp);
                relu_dot(acc[a][1], hiv[a], hj1, wp);
            }
        }
    }

    // entmax-1.5 pair closed form + affine output + zero diagonal
    const float tb   = 0.25f * (b2[2 * k] - b2[2 * k + 1]);
    const float w30  = W3[2 * k], w31 = W3[2 * k + 1];
    const float base = w31 + b3[k];
    const float dw3  = w30 - w31;
    const size_t outb = (size_t)(b * 8 + k) * 65536;

    #pragma unroll
    for (int a = 0; a < 4; ++a) {
        int gi = i0 + ti * 4 + a;
        #pragma unroll
        for (int u = 0; u < 2; ++u) {
            int gj = j0 + tj + 16 * u;
            float lo, hi; f2_unpack(acc[a][u], lo, hi);
            float tv   = lo + hi + tb;
            float dabs = fabsf(tv);
            float s    = sqrtf(fmaxf(0.5f - dabs * dabs, 0.0f));
            float q    = s + tv;
            float p0   = (dabs >= 0.5f) ? (tv > 0.0f ? 1.0f : 0.0f) : q * q;
            float res  = base + dw3 * p0;
            if (gi == gj) res = 0.0f;
            out[outb + (size_t)gi * 256 + gj] = res;
        }
    }
}

extern "C" void kernel_launch(void* const* d_in, const int* in_sizes, int n_in,
                              void* d_out, int out_size) {
    const float* E  = (const float*)d_in[0];   // (8, 256, 128)
    const float* W1 = (const float*)d_in[1];   // (8, 256, 128)
    const float* b1 = (const float*)d_in[2];   // (8, 128)
    const float* W2 = (const float*)d_in[3];   // (8, 128, 2)
    const float* b2 = (const float*)d_in[4];   // (8, 2)
    const float* W3 = (const float*)d_in[5];   // (8, 2, 1)
    const float* b3 = (const float*)d_in[6];   // (8, 1)
    float* out = (float*)d_out;                // (8, 8, 256, 256)

    cudaFuncSetAttribute(k2_pairs, cudaFuncAttributeMaxDynamicSharedMemorySize,
                         K2_SMEM_BYTES);

    k1_gemm<<<dim3(16, 16), 256>>>(E, W1, b1);
    k2_pairs<<<dim3(8, 4, 64), 256, K2_SMEM_BYTES>>>(W2, b2, W3, b3, out);
}

// round 12
// speedup vs baseline: 1.0428x; 1.0428x over previous
#include <cuda_runtime.h>
#include <cuda_bf16.h>
#include <cstdint>
#include <cstring>

typedef unsigned long long u64;

// Scratch: packed float2 h-pairs, layout [sk][b][hp][n]
//   sk = side*8 + k (side0 = HI, side1 = HJ + b1), b 0..7, hp 0..63, n 0..255
__device__ __align__(16) float2 g_H2[16u * 8u * 64u * 256u];   // 16 MB (L2-resident)

// ---------------------------------------------------------------------------
// helpers
// ---------------------------------------------------------------------------
static __device__ __forceinline__ void cpa16(void* dst, const void* src) {
    uint32_t d = (uint32_t)__cvta_generic_to_shared(dst);
    asm volatile("cp.async.cg.shared.global [%0], [%1], 16;" :: "r"(d), "l"(src));
}
static __device__ __forceinline__ void cpa_commit() {
    asm volatile("cp.async.commit_group;");
}
template<int N> static __device__ __forceinline__ void cpa_wait() {
    asm volatile("cp.async.wait_group %0;" :: "n"(N));
}
static __device__ __forceinline__ void f2_unpack(u64 v, float& lo, float& hi) {
    asm("mov.b64 {%0, %1}, %2;" : "=f"(lo), "=f"(hi) : "l"(v));
}
// acc += relu(hs + hj) * wp  per f32 lane; single asm block so ptxas can
// register-rename the pack/unpack movs.
static __device__ __forceinline__ void relu_dot(u64& acc, u64 hs, u64 hj, u64 wp) {
    asm("{\n\t"
        ".reg .f32 lo, hi;\n\t"
        ".reg .b64 s;\n\t"
        "add.rn.f32x2 s, %1, %2;\n\t"
        "mov.b64 {lo, hi}, s;\n\t"
        "max.f32 lo, lo, 0f00000000;\n\t"
        "max.f32 hi, hi, 0f00000000;\n\t"
        "mov.b64 s, {lo, hi};\n\t"
        "fma.rn.f32x2 %0, s, %3, %0;\n\t"
        "}" : "+l"(acc) : "l"(hs), "l"(hj), "l"(wp));
}

// ---------------------------------------------------------------------------
// Kernel 1: HI / HJB = E @ W1_slice (+ b1 for side 1).
// Same pipeline as R10; A-side smem reads merged into LDS.128 (v pairs).
// ---------------------------------------------------------------------------
__global__ void __launch_bounds__(256, 2)
k1_gemm(const float* __restrict__ E, const float* __restrict__ W1,
        const float* __restrict__ b1)
{
    __shared__ __align__(16) float2 aS[2][16][128];  // [buf][d][m] dup, 32KB
    __shared__ __align__(16) float  bS[2][16][128];  // [buf][d][h],      16KB

    const int t     = threadIdx.x;
    const int mtile = blockIdx.x;          // 0..15
    const int sk    = blockIdx.y;          // 0..15
    const int k     = sk & 7;
    const int side  = sk >> 3;
    const float* Wb = W1 + (size_t)k * 32768 + (size_t)side * 16384; // [d][h]

    const int tn = t & 15, tm = t >> 4;        // compute mapping
    const int arow = t >> 2, adq = t & 3;      // A loader
    const int bd = t >> 5, bq = t & 31;        // B loader
    const int bd2 = bd + 8;

    u64 acc[8][4];
    #pragma unroll
    for (int v = 0; v < 8; ++v)
        #pragma unroll
        for (int u = 0; u < 4; ++u) acc[v][u] = 0ULL;

    // --- prologue ---
    float4 rA0, rA1;
    rA0 = *(const float4*)(E + (size_t)(mtile * 128 + arow) * 128 + 0 + adq * 4);
    rA1 = *(const float4*)(E + (size_t)(mtile * 128 + arow + 64) * 128 + 0 + adq * 4);
    {
        float x[4] = {rA0.x, rA0.y, rA0.z, rA0.w};
        float y[4] = {rA1.x, rA1.y, rA1.z, rA1.w};
        #pragma unroll
        for (int q = 0; q < 4; ++q) {
            aS[0][adq * 4 + q][arow]      = make_float2(x[q], x[q]);
            aS[0][adq * 4 + q][arow + 64] = make_float2(y[q], y[q]);
        }
    }
    rA0 = *(const float4*)(E + (size_t)(mtile * 128 + arow) * 128 + 16 + adq * 4);
    rA1 = *(const float4*)(E + (size_t)(mtile * 128 + arow + 64) * 128 + 16 + adq * 4);
    #pragma unroll
    for (int c = 0; c < 2; ++c) {
        cpa16(&bS[c][bd][bq * 4],  Wb + (size_t)(c * 16 + bd)  * 128 + bq * 4);
        cpa16(&bS[c][bd2][bq * 4], Wb + (size_t)(c * 16 + bd2) * 128 + bq * 4);
        cpa_commit();
    }

    #pragma unroll
    for (int c = 0; c < 8; ++c) {
        if (c < 7) cpa_wait<1>(); else cpa_wait<0>();
        __syncthreads();
        if (c + 1 < 8) {
            float x[4] = {rA0.x, rA0.y, rA0.z, rA0.w};
            float y[4] = {rA1.x, rA1.y, rA1.z, rA1.w};
            int nb = (c + 1) & 1;
            #pragma unroll
            for (int q = 0; q < 4; ++q) {
                aS[nb][adq * 4 + q][arow]      = make_float2(x[q], x[q]);
                aS[nb][adq * 4 + q][arow + 64] = make_float2(y[q], y[q]);
            }
        }
        const int buf = c & 1;
        #pragma unroll
        for (int d = 0; d < 16; ++d) {
            u64 b2r[4];
            #pragma unroll
            for (int u = 0; u < 4; ++u)
                b2r[u] = *(const u64*)&bS[buf][d][2 * (tn + 16 * u)];
            #pragma unroll
            for (int v = 0; v < 8; v += 2) {
                ulonglong2 ad2 = *(const ulonglong2*)&aS[buf][d][tm * 8 + v];
                #pragma unroll
                for (int u = 0; u < 4; ++u) {
                    asm("fma.rn.f32x2 %0, %1, %2, %0;"
                        : "+l"(acc[v][u]) : "l"(ad2.x), "l"(b2r[u]));
                    asm("fma.rn.f32x2 %0, %1, %2, %0;"
                        : "+l"(acc[v + 1][u]) : "l"(ad2.y), "l"(b2r[u]));
                }
            }
        }
        __syncthreads();
        if (c + 2 < 8) {
            int d0 = (c + 2) * 16;
            rA0 = *(const float4*)(E + (size_t)(mtile * 128 + arow) * 128 + d0 + adq * 4);
            rA1 = *(const float4*)(E + (size_t)(mtile * 128 + arow + 64) * 128 + d0 + adq * 4);
            cpa16(&bS[buf][bd][bq * 4],  Wb + (size_t)(d0 + bd)  * 128 + bq * 4);
            cpa16(&bS[buf][bd2][bq * 4], Wb + (size_t)(d0 + bd2) * 128 + bq * 4);
            cpa_commit();
        }
    }

    // epilogue: add b1 pair (side 1), store transposed [sk][b][hp][n]
    const int b     = mtile >> 1;
    const int nbase = (mtile & 1) * 128 + tm * 8;
    const float* b1k = b1 + k * 128;
    #pragma unroll
    for (int u = 0; u < 4; ++u) {
        int hp = tn + 16 * u;
        float bx = 0.0f, by = 0.0f;
        if (side) { bx = b1k[2 * hp]; by = b1k[2 * hp + 1]; }
        size_t rowbase = ((size_t)(sk * 8 + b) * 64 + hp) * 256;
        #pragma unroll
        for (int v = 0; v < 8; ++v) {
            float lo, hi; f2_unpack(acc[v][u], lo, hi);
            g_H2[rowbase + nbase + v] = make_float2(lo + bx, hi + by);
        }
    }
}

// ---------------------------------------------------------------------------
// Kernel 2: pair loop + entmax-1.5 closed form.
// R10 tiling (64i x 64j, 256 threads, 4i x 4j per thread, 3 blocks/SM),
// with: blocked-j mapping (j = 4*tj + u) so hj loads are 2x LDS.128,
// unroll-8 p-loop for cross-iteration LDS hoisting, float4 output stores.
// Dynamic smem:
//   hiS: float2 [64][64] at      0  (32768 B)
//   hjS: float2 [64][64] at  32768  (32768 B)
//   w2S: float2 [64]     at  65536  (  512 B)
// ---------------------------------------------------------------------------
#define K2_SMEM_BYTES (32768 + 32768 + 512)

__global__ void __launch_bounds__(256, 3)
k2_pairs(const float* __restrict__ W2, const float* __restrict__ b2,
         const float* __restrict__ W3, const float* __restrict__ b3,
         float* __restrict__ out)
{
    extern __shared__ __align__(16) char smem[];
    float2 (*hiS)[64] = (float2(*)[64])(smem);
    float2 (*hjS)[64] = (float2(*)[64])(smem + 32768);
    float2* w2S       = (float2*)(smem + 65536);

    const int t  = threadIdx.x;
    const int z  = blockIdx.z;
    const int b  = z >> 3, k = z & 7;
    const int i0 = blockIdx.y * 64;
    const int j0 = blockIdx.x * 64;

    if (t < 64) {
        const float* w2k = W2 + k * 256;   // [h][c]
        w2S[t] = make_float2(0.25f * (w2k[4 * t + 0] - w2k[4 * t + 1]),
                             0.25f * (w2k[4 * t + 2] - w2k[4 * t + 3]));
    }

    const float2* hib = g_H2 + ((size_t)(k * 8 + b) * 64) * 256 + i0;        // side 0
    const float2* hjb = g_H2 + ((size_t)((8 + k) * 8 + b) * 64) * 256 + j0;  // side 1

    // load both 64hp x 64 tiles: 8 x 16B per thread per tile
    #pragma unroll
    for (int r = 0; r < 8; ++r) {
        int o = t + 256 * r;
        int p = o >> 5, q = o & 31;          // q in 16B units (2 float2)
        cpa16(&hiS[p][q * 2], hib + (size_t)p * 256 + q * 2);
        cpa16(&hjS[p][q * 2], hjb + (size_t)p * 256 + q * 2);
    }
    cpa_commit();

    u64 acc[4][4];
    #pragma unroll
    for (int a = 0; a < 4; ++a)
        #pragma unroll
        for (int u = 0; u < 4; ++u) acc[a][u] = 0ULL;

    cpa_wait<0>();
    __syncthreads();    // the only barrier in the kernel

    const int tj = t & 15, ti = t >> 4;   // thread's j quad = 4*tj.., i quad = 4*ti..

    #pragma unroll 8
    for (int p = 0; p < 64; ++p) {
        u64 wp = *(const u64*)&w2S[p];
        ulonglong2 h01  = *(const ulonglong2*)&hiS[p][ti * 4];
        ulonglong2 h23  = *(const ulonglong2*)&hiS[p][ti * 4 + 2];
        ulonglong2 hj01 = *(const ulonglong2*)&hjS[p][tj * 4];
        ulonglong2 hj23 = *(const ulonglong2*)&hjS[p][tj * 4 + 2];
        u64 hiv[4] = {h01.x, h01.y, h23.x, h23.y};
        u64 hjv[4] = {hj01.x, hj01.y, hj23.x, hj23.y};
        #pragma unroll
        for (int u = 0; u < 4; ++u)
            #pragma unroll
            for (int a = 0; a < 4; ++a)
                relu_dot(acc[a][u], hiv[a], hjv[u], wp);
    }

    // entmax-1.5 pair closed form + affine output + zero diagonal
    const float tb   = 0.25f * (b2[2 * k] - b2[2 * k + 1]);
    const float w30  = W3[2 * k], w31 = W3[2 * k + 1];
    const float base = w31 + b3[k];
    const float dw3  = w30 - w31;
    const size_t outb = (size_t)(b * 8 + k) * 65536;

    #pragma unroll
    for (int a = 0; a < 4; ++a) {
        int gi = i0 + ti * 4 + a;
        float4 res4;
        float* rp = (float*)&res4;
        #pragma unroll
        for (int u = 0; u < 4; ++u) {
            int gj = j0 + tj * 4 + u;
            float lo, hi; f2_unpack(acc[a][u], lo, hi);
            float tv   = lo + hi + tb;
            float dabs = fabsf(tv);
            float s    = sqrtf(fmaxf(0.5f - dabs * dabs, 0.0f));
            float q    = s + tv;
            float p0   = (dabs >= 0.5f) ? (tv > 0.0f ? 1.0f : 0.0f) : q * q;
            float res  = base + dw3 * p0;
            if (gi == gj) res = 0.0f;
            rp[u] = res;
        }
        *(float4*)(out + outb + (size_t)gi * 256 + j0 + tj * 4) = res4;
    }
}

extern "C" void kernel_launch(void* const* d_in, const int* in_sizes, int n_in,
                              void* d_out, int out_size) {
    const float* E  = (const float*)d_in[0];   // (8, 256, 128)
    const float* W1 = (const float*)d_in[1];   // (8, 256, 128)
    const float* b1 = (const float*)d_in[2];   // (8, 128)
    const float* W2 = (const float*)d_in[3];   // (8, 128, 2)
    const float* b2 = (const float*)d_in[4];   // (8, 2)
    const float* W3 = (const float*)d_in[5];   // (8, 2, 1)
    const float* b3 = (const float*)d_in[6];   // (8, 1)
    float* out = (float*)d_out;                // (8, 8, 256, 256)

    cudaFuncSetAttribute(k2_pairs, cudaFuncAttributeMaxDynamicSharedMemorySize,
                         K2_SMEM_BYTES);

    k1_gemm<<<dim3(16, 16), 256>>>(E, W1, b1);
    k2_pairs<<<dim3(4, 4, 64), 256, K2_SMEM_BYTES>>>(W2, b2, W3, b3, out);
}

// round 15
// speedup vs baseline: 1.2517x; 1.2004x over previous
#include <cuda_runtime.h>
#include <cuda_bf16.h>
#include <cstdint>
#include <cstring>

typedef unsigned long long u64;

// ---------------------------------------------------------------------------
// Device scratch
// ---------------------------------------------------------------------------
// H2: packed float2 h-pairs, layout [sk][b][hp][n]
//   sk = side*8 + k (side0 = HI, side1 = HJ + b1), b 0..7, hp 0..63, n 0..255
__device__ __align__(16) float2 g_H2[16u * 8u * 64u * 256u];   // 16 MB

// bf16 hi/lo split images, pre-swizzled for k1's smem layout.
// 32 tiles x 32KB. tiles 0..15 = E mtiles (row=m, col=d); 16..31 = W sk-tiles
// (row=h, col=d). Per tile: 2 K-chunks of 16KB (cols 0-63, 64-127); within a
// chunk: row r (128B = 64 bf16), 16B groups XOR-swizzled: grp ^= (r & 7).
__device__ __align__(16) unsigned char g_BFH[32u * 32768u];    // 1 MB
__device__ __align__(16) unsigned char g_BFL[32u * 32768u];    // 1 MB

// ---------------------------------------------------------------------------
// helpers
// ---------------------------------------------------------------------------
static __device__ __forceinline__ void cpa16(void* dst, const void* src) {
    uint32_t d = (uint32_t)__cvta_generic_to_shared(dst);
    asm volatile("cp.async.cg.shared.global [%0], [%1], 16;" :: "r"(d), "l"(src));
}
static __device__ __forceinline__ void cpa_commit() {
    asm volatile("cp.async.commit_group;");
}
template<int N> static __device__ __forceinline__ void cpa_wait() {
    asm volatile("cp.async.wait_group %0;" :: "n"(N));
}
static __device__ __forceinline__ void f2_unpack(u64 v, float& lo, float& hi) {
    asm("mov.b64 {%0, %1}, %2;" : "=f"(lo), "=f"(hi) : "l"(v));
}
static __device__ __forceinline__ void relu_dot(u64& acc, u64 hs, u64 hj, u64 wp) {
    asm("{\n\t"
        ".reg .f32 lo, hi;\n\t"
        ".reg .b64 s;\n\t"
        "add.rn.f32x2 s, %1, %2;\n\t"
        "mov.b64 {lo, hi}, s;\n\t"
        "max.f32 lo, lo, 0f00000000;\n\t"
        "max.f32 hi, hi, 0f00000000;\n\t"
        "mov.b64 s, {lo, hi};\n\t"
        "fma.rn.f32x2 %0, s, %3, %0;\n\t"
        "}" : "+l"(acc) : "l"(hs), "l"(hj), "l"(wp));
}
static __device__ __forceinline__ uint32_t smem_u32(const void* p) {
    return (uint32_t)__cvta_generic_to_shared(p);
}
static __device__ __forceinline__ void ldsm_x4(uint32_t addr, uint32_t* r) {
    asm volatile("ldmatrix.sync.aligned.m8n8.x4.shared.b16 {%0,%1,%2,%3}, [%4];"
                 : "=r"(r[0]), "=r"(r[1]), "=r"(r[2]), "=r"(r[3]) : "r"(addr));
}
static __device__ __forceinline__ void mma16816(float* c, const uint32_t* a,
                                                uint32_t b0, uint32_t b1) {
    asm volatile("mma.sync.aligned.m16n8k16.row.col.f32.bf16.bf16.f32 "
        "{%0,%1,%2,%3}, {%4,%5,%6,%7}, {%8,%9}, {%0,%1,%2,%3};"
        : "+f"(c[0]), "+f"(c[1]), "+f"(c[2]), "+f"(c[3])
        : "r"(a[0]), "r"(a[1]), "r"(a[2]), "r"(a[3]), "r"(b0), "r"(b1));
}

// ---------------------------------------------------------------------------
// Kernel 0: split E and W1 into bf16 hi/lo pre-swizzled images.
// 65536 threads; each handles one 16B group (8 cols) of one row of one tile.
// ---------------------------------------------------------------------------
__global__ void __launch_bounds__(256)
k0_prep(const float* __restrict__ E, const float* __restrict__ W1)
{
    int id   = blockIdx.x * 256 + threadIdx.x;
    int tile = id >> 11;            // 0..31
    int g    = id & 2047;
    int r    = g >> 4;              // 0..127
    int c0   = (g & 15) * 8;        // 0..120

    float v[8];
    if (tile < 16) {
        const float* src = E + ((size_t)(tile * 128 + r)) * 128 + c0;
        float4 x = *(const float4*)src;
        float4 y = *(const float4*)(src + 4);
        v[0] = x.x; v[1] = x.y; v[2] = x.z; v[3] = x.w;
        v[4] = y.x; v[5] = y.y; v[6] = y.z; v[7] = y.w;
    } else {
        int sk = tile - 16, k = sk & 7, side = sk >> 3;
        // W tile value(row=h=r, col=d) = W1[k][side*128 + d][r]
        const float* base = W1 + (size_t)k * 32768 + (size_t)(side * 128 + c0) * 128 + r;
        #pragma unroll
        for (int q = 0; q < 8; ++q) v[q] = base[q * 128];
    }

    uint32_t hw[4], lw[4];
    #pragma unroll
    for (int q = 0; q < 4; ++q) {
        float a0 = v[2 * q], a1 = v[2 * q + 1];
        __nv_bfloat16 h0 = __float2bfloat16(a0);
        __nv_bfloat16 h1 = __float2bfloat16(a1);
        __nv_bfloat16 l0 = __float2bfloat16(a0 - __bfloat162float(h0));
        __nv_bfloat16 l1 = __float2bfloat16(a1 - __bfloat162float(h1));
        hw[q] = (uint32_t)__bfloat16_as_ushort(h0) | ((uint32_t)__bfloat16_as_ushort(h1) << 16);
        lw[q] = (uint32_t)__bfloat16_as_ushort(l0) | ((uint32_t)__bfloat16_as_ushort(l1) << 16);
    }

    // chunked + swizzled image offset
    uint32_t grp = (uint32_t)((c0 >> 3) & 7) ^ (uint32_t)(r & 7);
    uint32_t off = (uint32_t)tile * 32768u + (uint32_t)(c0 >> 6) * 16384u
                 + (uint32_t)r * 128u + grp * 16u;
    *(uint4*)(g_BFH + off) = make_uint4(hw[0], hw[1], hw[2], hw[3]);
    *(uint4*)(g_BFL + off) = make_uint4(lw[0], lw[1], lw[2], lw[3]);
}

// ---------------------------------------------------------------------------
// Kernel 1: bf16x3-split GEMM via mma.sync.m16n8k16 (sm_80+ PTX, tensor pipe).
// Per block: one (mtile, sk): D[128m,128h] = Eh@Wh^T + Eh@Wl^T + El@Wh^T.
// 8 warps, warp tile 32m x 64h; 2 K-chunks of 64; smem 64KB, 2 blocks/SM.
// Epilogue: +b1 (side 1), pack adjacent-h pairs (native in the acc frag),
// store g_H2 transposed.
// smem: [Eh 16K][El 16K][Wh 16K][Wl 16K]
// ---------------------------------------------------------------------------
#define K1_SMEM_BYTES 65536

__global__ void __launch_bounds__(256, 2)
k1_mma(const float* __restrict__ b1)
{
    extern __shared__ __align__(16) char dsm[];
    __shared__ float s_b1[128];

    const int t      = threadIdx.x;
    const int wid    = t >> 5, lane = t & 31;
    const int mtile  = blockIdx.x;     // 0..15
    const int sk     = blockIdx.y;     // 0..15
    const int k      = sk & 7, side = sk >> 3;
    const int warp_m = wid & 3, warp_n = wid >> 2;

    if (t < 128) s_b1[t] = side ? b1[k * 128 + t] : 0.0f;

    const unsigned char* src0 = g_BFH + (size_t)mtile * 32768;       // Eh
    const unsigned char* src1 = g_BFL + (size_t)mtile * 32768;       // El
    const unsigned char* src2 = g_BFH + (size_t)(16 + sk) * 32768;   // Wh
    const unsigned char* src3 = g_BFL + (size_t)(16 + sk) * 32768;   // Wl

    const uint32_t sbase = smem_u32(dsm);
    const int r15 = lane & 15, hi16 = lane >> 4;

    float acc[2][8][4];
    #pragma unroll
    for (int mf = 0; mf < 2; ++mf)
        #pragma unroll
        for (int nf = 0; nf < 8; ++nf)
            #pragma unroll
            for (int q = 0; q < 4; ++q) acc[mf][nf][q] = 0.0f;

    #pragma unroll
    for (int ch = 0; ch < 2; ++ch) {
        if (ch) __syncthreads();   // everyone done reading previous chunk
        // load 4 x 16KB sub-tiles; thread t copies 16 x 16B
        #pragma unroll
        for (int r = 0; r < 16; ++r) {
            const int loc = (r & 3) * 4096 + t * 16;
            const unsigned char* s =
                (r >> 2) == 0 ? src0 : (r >> 2) == 1 ? src1 : (r >> 2) == 2 ? src2 : src3;
            cpa16(dsm + (r >> 2) * 16384 + loc, s + ch * 16384 + loc);
        }
        cpa_commit();
        cpa_wait<0>();
        __syncthreads();

        #pragma unroll
        for (int pr = 0; pr < 3; ++pr) {
            const uint32_t aA = sbase + (pr == 2 ? 16384 : 0);           // Eh,Eh,El
            const uint32_t aB = sbase + 32768 + (pr == 1 ? 16384 : 0);   // Wh,Wl,Wh
            #pragma unroll
            for (int ks = 0; ks < 4; ++ks) {
                const int g = 2 * ks + hi16;
                uint32_t af[2][4];
                #pragma unroll
                for (int mf = 0; mf < 2; ++mf) {
                    int row = warp_m * 32 + mf * 16 + r15;
                    uint32_t addr = aA + row * 128 + (((uint32_t)g ^ (row & 7)) << 4);
                    ldsm_x4(addr, af[mf]);
                }
                #pragma unroll
                for (int nf16 = 0; nf16 < 4; ++nf16) {
                    int row = warp_n * 64 + nf16 * 16 + r15;
                    uint32_t addr = aB + row * 128 + (((uint32_t)g ^ (row & 7)) << 4);
                    uint32_t bf[4];
                    ldsm_x4(addr, bf);
                    #pragma unroll
                    for (int mf = 0; mf < 2; ++mf) {
                        mma16816(acc[mf][2 * nf16 + 0], af[mf], bf[0], bf[2]);
                        mma16816(acc[mf][2 * nf16 + 1], af[mf], bf[1], bf[3]);
                    }
                }
            }
        }
    }

    // epilogue: acc frag (c0,c1) = adjacent h pair at row lane>>2, (c2,c3) at +8
    const int b     = mtile >> 1;
    const int nbase = (mtile & 1) * 128;
    #pragma unroll
    for (int mf = 0; mf < 2; ++mf) {
        int row0 = warp_m * 32 + mf * 16 + (lane >> 2);
        #pragma unroll
        for (int nf = 0; nf < 8; ++nf) {
            int hcol = warp_n * 64 + nf * 8 + 2 * (lane & 3);
            int hp   = hcol >> 1;
            float bb0 = s_b1[hcol], bb1 = s_b1[hcol + 1];
            size_t base = ((size_t)(sk * 8 + b) * 64 + hp) * 256 + nbase;
            g_H2[base + row0]     = make_float2(acc[mf][nf][0] + bb0, acc[mf][nf][1] + bb1);
            g_H2[base + row0 + 8] = make_float2(acc[mf][nf][2] + bb0, acc[mf][nf][3] + bb1);
        }
    }
}

// ---------------------------------------------------------------------------
// Kernel 2: pair loop + entmax-1.5 closed form. UNCHANGED from R12 (best).
// ---------------------------------------------------------------------------
#define K2_SMEM_BYTES (32768 + 32768 + 512)

__global__ void __launch_bounds__(256, 3)
k2_pairs(const float* __restrict__ W2, const float* __restrict__ b2,
         const float* __restrict__ W3, const float* __restrict__ b3,
         float* __restrict__ out)
{
    extern __shared__ __align__(16) char smem[];
    float2 (*hiS)[64] = (float2(*)[64])(smem);
    float2 (*hjS)[64] = (float2(*)[64])(smem + 32768);
    float2* w2S       = (float2*)(smem + 65536);

    const int t  = threadIdx.x;
    const int z  = blockIdx.z;
    const int b  = z >> 3, k = z & 7;
    const int i0 = blockIdx.y * 64;
    const int j0 = blockIdx.x * 64;

    if (t < 64) {
        const float* w2k = W2 + k * 256;   // [h][c]
        w2S[t] = make_float2(0.25f * (w2k[4 * t + 0] - w2k[4 * t + 1]),
                             0.25f * (w2k[4 * t + 2] - w2k[4 * t + 3]));
    }

    const float2* hib = g_H2 + ((size_t)(k * 8 + b) * 64) * 256 + i0;        // side 0
    const float2* hjb = g_H2 + ((size_t)((8 + k) * 8 + b) * 64) * 256 + j0;  // side 1

    #pragma unroll
    for (int r = 0; r < 8; ++r) {
        int o = t + 256 * r;
        int p = o >> 5, q = o & 31;
        cpa16(&hiS[p][q * 2], hib + (size_t)p * 256 + q * 2);
        cpa16(&hjS[p][q * 2], hjb + (size_t)p * 256 + q * 2);
    }
    cpa_commit();

    u64 acc[4][4];
    #pragma unroll
    for (int a = 0; a < 4; ++a)
        #pragma unroll
        for (int u = 0; u < 4; ++u) acc[a][u] = 0ULL;

    cpa_wait<0>();
    __syncthreads();

    const int tj = t & 15, ti = t >> 4;

    #pragma unroll 8
    for (int p = 0; p < 64; ++p) {
        u64 wp = *(const u64*)&w2S[p];
        ulonglong2 h01  = *(const ulonglong2*)&hiS[p][ti * 4];
        ulonglong2 h23  = *(const ulonglong2*)&hiS[p][ti * 4 + 2];
        ulonglong2 hj01 = *(const ulonglong2*)&hjS[p][tj * 4];
        ulonglong2 hj23 = *(const ulonglong2*)&hjS[p][tj * 4 + 2];
        u64 hiv[4] = {h01.x, h01.y, h23.x, h23.y};
        u64 hjv[4] = {hj01.x, hj01.y, hj23.x, hj23.y};
        #pragma unroll
        for (int u = 0; u < 4; ++u)
            #pragma unroll
            for (int a = 0; a < 4; ++a)
                relu_dot(acc[a][u], hiv[a], hjv[u], wp);
    }

    const float tb   = 0.25f * (b2[2 * k] - b2[2 * k + 1]);
    const float w30  = W3[2 * k], w31 = W3[2 * k + 1];
    const float base = w31 + b3[k];
    const float dw3  = w30 - w31;
    const size_t outb = (size_t)(b * 8 + k) * 65536;

    #pragma unroll
    for (int a = 0; a < 4; ++a) {
        int gi = i0 + ti * 4 + a;
        float4 res4;
        float* rp = (float*)&res4;
        #pragma unroll
        for (int u = 0; u < 4; ++u) {
            int gj = j0 + tj * 4 + u;
            float lo, hi; f2_unpack(acc[a][u], lo, hi);
            float tv   = lo + hi + tb;
            float dabs = fabsf(tv);
            float s    = sqrtf(fmaxf(0.5f - dabs * dabs, 0.0f));
            float q    = s + tv;
            float p0   = (dabs >= 0.5f) ? (tv > 0.0f ? 1.0f : 0.0f) : q * q;
            float res  = base + dw3 * p0;
            if (gi == gj) res = 0.0f;
            rp[u] = res;
        }
        *(float4*)(out + outb + (size_t)gi * 256 + j0 + tj * 4) = res4;
    }
}

extern "C" void kernel_launch(void* const* d_in, const int* in_sizes, int n_in,
                              void* d_out, int out_size) {
    const float* E  = (const float*)d_in[0];   // (8, 256, 128)
    const float* W1 = (const float*)d_in[1];   // (8, 256, 128)
    const float* b1 = (const float*)d_in[2];   // (8, 128)
    const float* W2 = (const float*)d_in[3];   // (8, 128, 2)
    const float* b2 = (const float*)d_in[4];   // (8, 2)
    const float* W3 = (const float*)d_in[5];   // (8, 2, 1)
    const float* b3 = (const float*)d_in[6];   // (8, 1)
    float* out = (float*)d_out;                // (8, 8, 256, 256)

    cudaFuncSetAttribute(k1_mma, cudaFuncAttributeMaxDynamicSharedMemorySize,
                         K1_SMEM_BYTES);
    cudaFuncSetAttribute(k2_pairs, cudaFuncAttributeMaxDynamicSharedMemorySize,
                         K2_SMEM_BYTES);

    k0_prep<<<256, 256>>>(E, W1);
    k1_mma<<<dim3(16, 16), 256, K1_SMEM_BYTES>>>(b1);
    k2_pairs<<<dim3(4, 4, 64), 256, K2_SMEM_BYTES>>>(W2, b2, W3, b3, out);
}